// round 13
// baseline (speedup 1.0000x reference)
#include <cuda_runtime.h>
#include <cooperative_groups.h>

namespace cg = cooperative_groups;

// iPUNet forward, SINGLE cooperative kernel with grid.sync().
//
// Phase A: each CTA computes Y[p][0..26] for its points (strided):
//   j<21 : feat[p] . W_unet[:, j/3, j%3]
//   j=21..26 : raw oris/nors dots (+bias)
//   lane j -> output j, warp w -> channel block w: Wu loads are
//   lane-consecutive (84B run), feat is a broadcast smem read.
// grid.sync()  (official cooperative barrier: co-residency validated at
//   launch; errors loudly if impossible -- cannot hang)
// Phase B: per-point pipeline (ball query, rotation from own Y row,
//   cells, winner Y gather, outputs) == the proven 8.4us main kernel.
//
// Shapes: B=2, N=1024, FEAT=128, NSAMPLE=48, GRID=7, RADIUS=0.3
// Output (f32, 417792 elems):
//   oris [0,6144) | nors [6144,12288) | pts_ups [12288,110592)
//   pts_offset [110592,116736) | pts_up [116736,417792)

#define NPTS   1024
#define FEATD  128
#define NS     48
#define YSTR   32
#define TOTALP 2048

#define OFF_ORIS   0
#define OFF_NORS   6144
#define OFF_UPS    12288
#define OFF_OFFSET 110592
#define OFF_PTSUP  116736

__device__ __align__(128) float g_Y[TOTALP * YSTR];

__global__ __launch_bounds__(128)
void ipunet_kernel(const float* __restrict__ xyz,
                   const float* __restrict__ feat,
                   const float* __restrict__ W0, const float* __restrict__ b0,
                   const float* __restrict__ W1, const float* __restrict__ b1,
                   const float* __restrict__ Wu, const int* __restrict__ g_index,
                   float* __restrict__ out)
{
    const int G    = gridDim.x;
    const int t    = threadIdx.x;      // 0..127
    const int lane = t & 31;
    const int warp = t >> 5;           // 0..3

    __shared__ float    s_f[FEATD];
    __shared__ float    s_acc[4][27];
    __shared__ float    s_rot[9];
    __shared__ unsigned s_mask[32];
    __shared__ int      s_nbr[NS];
    __shared__ int      s_win[91];
    __shared__ int      s_cnt;
    __shared__ float    s_off[49 * 3];
    __shared__ unsigned s_upmask[49];

    // ---------------- Phase A: Y rows for my points ---------------------------
    for (int p = blockIdx.x; p < TOTALP; p += G) {
        s_f[t] = __ldg(&feat[(p << 7) + t]);
        __syncthreads();
        if (lane < 27) {
            const float* w;
            int stride;
            if (lane < 21)      { w = Wu + lane;               stride = 21; }
            else if (lane < 24) { w = W0 + ((lane - 21) << 7); stride = 1;  }
            else                { w = W1 + ((lane - 24) << 7); stride = 1;  }
            const int c0 = warp << 5;
            float acc = 0.0f;
#pragma unroll 8
            for (int i = 0; i < 32; i++)
                acc += s_f[c0 + i] * __ldg(&w[(c0 + i) * stride]);
            s_acc[warp][lane] = acc;
        }
        __syncthreads();
        if (t < 27) {
            float y = s_acc[0][t] + s_acc[1][t] + s_acc[2][t] + s_acc[3][t];
            if (t >= 24)      y += __ldg(&b1[t - 24]);
            else if (t >= 21) y += __ldg(&b0[t - 21]);
            g_Y[p * YSTR + t] = y;
        }
        __syncthreads();
    }

    // ---------------- official grid-wide barrier -------------------------------
    cg::this_grid().sync();

    // ---------------- upmask (point-independent, once) --------------------------
    if (t < 49) s_upmask[t] = 0u;
    __syncthreads();
    if (t >= 64 && t < 80)
        atomicOr(&s_upmask[__ldg(&g_index[t - 64])], 1u << (t - 64));

    // ---------------- Phase B: per-point pipeline --------------------------------
    for (int p = blockIdx.x; p < TOTALP; p += G) {
        const int b   = p >> 10;
        const int pid = p & 1023;
        const float* xb = xyz + b * 3 * NPTS;
        const float cx = __ldg(&xb[pid]);
        const float cy = __ldg(&xb[NPTS + pid]);
        const float cz = __ldg(&xb[2 * NPTS + pid]);
        const float c2 = cx * cx + cy * cy + cz * cz;

        if (t < 91) s_win[t] = -1;
        s_off[t] = 0.0f;
        if (t < 19) s_off[128 + t] = 0.0f;

        // ball query: 1024-bit mask via ballot
#pragma unroll
        for (int seg = 0; seg < 8; seg++) {
            int j = seg * 128 + t;
            float px = __ldg(&xb[j]);
            float py = __ldg(&xb[NPTS + j]);
            float pz = __ldg(&xb[2 * NPTS + j]);
            float d = -2.0f * (cx * px + cy * py + cz * pz) + c2
                      + (px * px + py * py + pz * pz);
            unsigned m = __ballot_sync(0xffffffffu, !(d > 0.09f));
            if (lane == 0) s_mask[seg * 4 + warp] = m;
        }
        __syncthreads();

        // concurrent: rotation (t==32, reads OWN Y row) | extraction (warp 0)
        if (t == 32) {
            const float* yp = g_Y + p * YSTR + 21;
            float ov[3] = { yp[0], yp[1], yp[2] };
            float nv[3] = { yp[3], yp[4], yp[5] };

            float io = 1.0f / (sqrtf(ov[0]*ov[0]+ov[1]*ov[1]+ov[2]*ov[2] + 1e-8f) + 1e-10f);
            ov[0] *= io; ov[1] *= io; ov[2] *= io;
            float in = 1.0f / (sqrtf(nv[0]*nv[0]+nv[1]*nv[1]+nv[2]*nv[2] + 1e-8f) + 1e-10f);
            nv[0] *= in; nv[1] *= in; nv[2] *= in;

            float r90[3];
            r90[0] = ov[1]*nv[2] - ov[2]*nv[1];
            r90[1] = ov[2]*nv[0] - ov[0]*nv[2];
            r90[2] = ov[0]*nv[1] - ov[1]*nv[0];
            float ir = 1.0f / (sqrtf(r90[0]*r90[0]+r90[1]*r90[1]+r90[2]*r90[2] + 1e-8f) + 1e-10f);
            r90[0] *= ir; r90[1] *= ir; r90[2] *= ir;

            float o0[3];
            o0[0] = r90[1]*nv[2] - r90[2]*nv[1];
            o0[1] = r90[2]*nv[0] - r90[0]*nv[2];
            o0[2] = r90[0]*nv[1] - r90[1]*nv[0];
            float i0 = 1.0f / (sqrtf(o0[0]*o0[0]+o0[1]*o0[1]+o0[2]*o0[2] + 1e-8f) + 1e-10f);
            o0[0] *= i0; o0[1] *= i0; o0[2] *= i0;

            s_rot[0] = o0[0];  s_rot[1] = o0[1];  s_rot[2] = o0[2];
            s_rot[3] = r90[0]; s_rot[4] = r90[1]; s_rot[5] = r90[2];
            s_rot[6] = nv[0];  s_rot[7] = nv[1];  s_rot[8] = nv[2];

#pragma unroll
            for (int d = 0; d < 3; d++) {
                out[OFF_ORIS + p * 3 + d] = ov[d];
                out[OFF_NORS + p * 3 + d] = nv[d];
            }
        }
        if (warp == 0) {
            unsigned m = s_mask[lane];
            int pc = __popc(m);
            int incl = pc;
#pragma unroll
            for (int o = 1; o < 32; o <<= 1) {
                int v = __shfl_up_sync(0xffffffffu, incl, o);
                if (lane >= o) incl += v;
            }
            int excl = incl - pc;
            if (lane == 31) s_cnt = (incl < NS) ? incl : NS;
            unsigned mm = m;
            int r = excl;
            while (mm && r < NS) {
                int bpos = __ffs(mm) - 1;
                s_nbr[r] = (lane << 5) + bpos;
                mm &= mm - 1;
                r++;
            }
        }
        __syncthreads();

        // local coords -> cell; last-wins winner
        int myCell = -1, myJ = 0;
        if (t < NS) {
            myJ = (t < s_cnt) ? s_nbr[t] : s_nbr[0];
            float lx = __ldg(&xb[myJ]) - cx;
            float ly = __ldg(&xb[NPTS + myJ]) - cy;
            float lz = __ldg(&xb[2 * NPTS + myJ]) - cz;
            int c[3];
#pragma unroll
            for (int d = 0; d < 3; d++) {
                float lp = lx * s_rot[d*3+0] + ly * s_rot[d*3+1] + lz * s_rot[d*3+2];
                float v = rintf((lp + 0.3f) / 0.6f * 6.0f);
                int ci = (int)v;
                ci = ci < 0 ? 0 : (ci > 6 ? 6 : ci);
                c[d] = ci;
            }
            myCell = c[0] * 7 + c[1] * 7 + c[2];   // reference quirk: both *g
            atomicMax(&s_win[myCell], t);
        }
        __syncthreads();

        // winners gather Y row (3 floats) + accumulate
        if (t < NS && s_win[myCell] == t) {
            int k  = myCell % 7;
            int p5 = (myCell / 49) * 7 + (myCell / 7) % 7;
            const float* y = g_Y + ((b << 10) + myJ) * YSTR + k * 3;
            atomicAdd(&s_off[p5 * 3 + 0], __ldg(&y[0]));
            atomicAdd(&s_off[p5 * 3 + 1], __ldg(&y[1]));
            atomicAdd(&s_off[p5 * 3 + 2], __ldg(&y[2]));
        }
        __syncthreads();

        // up = vals + feat_off; rotate back; write outputs
        if (t < 49) {
            int s = t;
            float u0 = (float)(s / 7 - 3) * 0.1f + s_off[s * 3 + 0];
            float u1 = (float)(s % 7 - 3) * 0.1f + s_off[s * 3 + 1];
            float u2 = s_off[s * 3 + 2];
            float w[3];
#pragma unroll
            for (int d = 0; d < 3; d++)
                w[d] = u0 * s_rot[d] + u1 * s_rot[3 + d] + u2 * s_rot[6 + d]
                     + (d == 0 ? cx : (d == 1 ? cy : cz));

            float* o_up = out + OFF_PTSUP + (p * 49 + s) * 3;
            o_up[0] = w[0]; o_up[1] = w[1]; o_up[2] = w[2];

            if (s == 24) {
                float* o_of = out + OFF_OFFSET + p * 3;
                o_of[0] = w[0]; o_of[1] = w[1]; o_of[2] = w[2];
            }
            unsigned m = s_upmask[s];
            while (m) {
                int q = __ffs(m) - 1;
                m &= m - 1;
                float* o_u = out + OFF_UPS + (p * 16 + q) * 3;
                o_u[0] = w[0]; o_u[1] = w[1]; o_u[2] = w[2];
            }
        }
        __syncthreads();
    }
}

extern "C" void kernel_launch(void* const* d_in, const int* in_sizes, int n_in,
                              void* d_out, int out_size)
{
    const float* xyz   = (const float*)d_in[0];
    const float* feat  = (const float*)d_in[1];
    const float* W0    = (const float*)d_in[2];
    const float* b0    = (const float*)d_in[3];
    const float* W1    = (const float*)d_in[4];
    const float* b1    = (const float*)d_in[5];
    const float* Wu    = (const float*)d_in[6];
    const int*   index = (const int*)d_in[7];
    float* out = (float*)d_out;

    int dev = 0;
    cudaGetDevice(&dev);
    int nsm = 0;
    cudaDeviceGetAttribute(&nsm, cudaDevAttrMultiProcessorCount, dev);
    int maxb = 0;
    cudaOccupancyMaxActiveBlocksPerMultiprocessor(&maxb, ipunet_kernel, 128, 0);
    long cap = (long)maxb * (long)nsm;
    int grid = (cap < TOTALP) ? (int)cap : TOTALP;
    if (grid < 1) grid = 148;   // conservative fallback; cooperative launch
                                // will still validate residency loudly

    void* args[] = { (void*)&xyz, (void*)&feat, (void*)&W0, (void*)&b0,
                     (void*)&W1, (void*)&b1, (void*)&Wu, (void*)&index,
                     (void*)&out };
    cudaLaunchCooperativeKernel((void*)ipunet_kernel,
                                dim3(grid, 1, 1), dim3(128, 1, 1),
                                args, 0, (cudaStream_t)0);
}

// round 14
// speedup vs baseline: 1.4708x; 1.4708x over previous
#include <cuda_runtime.h>

// iPUNet forward, fully fused single kernel. One CTA (128 thr) per point.
// R11 base (13.06us) + W_unet stored TRANSPOSED in smem as [k][c][3] so each
// winner-block's 12 weights are 3x LDS.128 (conflict-free per quarter-warp
// phase) instead of 12 scalar LDS -- ~130 fewer instructions per warp.
//
// Shapes: B=2, N=1024, FEAT=128, NSAMPLE=48, GRID=7, RADIUS=0.3
// Output (f32, 417792 elems):
//   oris [0,6144) | nors [6144,12288) | pts_ups [12288,110592)
//   pts_offset [110592,116736) | pts_up [116736,417792)

#define NPTS   1024
#define FEATD  128
#define NS     48

#define OFF_ORIS   0
#define OFF_NORS   6144
#define OFF_UPS    12288
#define OFF_OFFSET 110592
#define OFF_PTSUP  116736

__device__ __forceinline__ float wredf(float x) {
#pragma unroll
    for (int o = 16; o; o >>= 1) x += __shfl_xor_sync(0xffffffffu, x, o);
    return x;
}

__global__ __launch_bounds__(128)
void ipunet_kernel(const float* __restrict__ xyz,
                   const float* __restrict__ feat,
                   const float* __restrict__ W0, const float* __restrict__ b0,
                   const float* __restrict__ W1, const float* __restrict__ b1,
                   const float* __restrict__ Wu, const int* __restrict__ g_index,
                   float* __restrict__ out)
{
    const int p    = blockIdx.x;       // global point id 0..2047
    const int b    = p >> 10;
    const int pid  = p & 1023;
    const int t    = threadIdx.x;      // 0..127
    const int lane = t & 31;
    const int warp = t >> 5;           // 0..3

    __shared__ float    s_wu[7 * FEATD * 3];  // TRANSPOSED: [k][c][3], 10.5 KB
    __shared__ float    s_rot[9];
    __shared__ unsigned s_mask[32];
    __shared__ int      s_nbr[NS];
    __shared__ int      s_win[91];
    __shared__ int      s_cnt;
    __shared__ int      s_nwin;
    __shared__ int      s_wlist[NS];    // packed (cell<<10)|nbr
    __shared__ float    s_off[49 * 3];
    __shared__ unsigned s_upmask[49];
    __shared__ float    s_part[4][6];

    // ---- center ----------------------------------------------------------------
    const float* xb = xyz + b * 3 * NPTS;
    const float cx = __ldg(&xb[pid]);
    const float cy = __ldg(&xb[NPTS + pid]);
    const float cz = __ldg(&xb[2 * NPTS + pid]);
    const float c2 = cx * cx + cy * cy + cz * cz;

    // ---- smem init ----------------------------------------------------------------
    if (t < 91) s_win[t] = -1;
    if (t == 0) s_nwin = 0;
    if (t < 49) s_upmask[t] = 0u;
    s_off[t] = 0.0f;
    if (t < 19) s_off[128 + t] = 0.0f;

    // ---- stage W_unet TRANSPOSED: thread t = channel c -----------------------------
    {
        const int c = t;
        const float* wr = &Wu[c * 21];
#pragma unroll
        for (int k = 0; k < 7; k++) {
            s_wu[k * 384 + c * 3 + 0] = __ldg(&wr[k * 3 + 0]);
            s_wu[k * 384 + c * 3 + 1] = __ldg(&wr[k * 3 + 1]);
            s_wu[k * 384 + c * 3 + 2] = __ldg(&wr[k * 3 + 2]);
        }
    }

    // ---- merged: ball query (8 segs) + oris/nors matvec -----------------------------
    {
        float f   = __ldg(&feat[(p << 7) + t]);
        float w0a = __ldg(&W0[t]), w0b = __ldg(&W0[128 + t]), w0c = __ldg(&W0[256 + t]);
        float w1a = __ldg(&W1[t]), w1b = __ldg(&W1[128 + t]), w1c = __ldg(&W1[256 + t]);

#pragma unroll
        for (int seg = 0; seg < 8; seg++) {
            int j = seg * 128 + t;
            float px = __ldg(&xb[j]);
            float py = __ldg(&xb[NPTS + j]);
            float pz = __ldg(&xb[2 * NPTS + j]);
            float d = -2.0f * (cx * px + cy * py + cz * pz) + c2
                      + (px * px + py * py + pz * pz);
            unsigned m = __ballot_sync(0xffffffffu, !(d > 0.09f));
            if (lane == 0) s_mask[seg * 4 + warp] = m;
        }

        float q0 = wredf(f * w0a), q1 = wredf(f * w0b), q2 = wredf(f * w0c);
        float q3 = wredf(f * w1a), q4 = wredf(f * w1b), q5 = wredf(f * w1c);
        if (lane == 0) {
            s_part[warp][0] = q0; s_part[warp][1] = q1; s_part[warp][2] = q2;
            s_part[warp][3] = q3; s_part[warp][4] = q4; s_part[warp][5] = q5;
        }
    }
    __syncthreads();

    // ---- concurrent: rotation (t==32) | extraction (warp 0) | upmask (warp 2) -------
    if (t >= 64 && t < 80)
        atomicOr(&s_upmask[__ldg(&g_index[t - 64])], 1u << (t - 64));

    if (t == 32) {
        float ov[3], nv[3];
#pragma unroll
        for (int d = 0; d < 3; d++) {
            ov[d] = s_part[0][d]   + s_part[1][d]   + s_part[2][d]   + s_part[3][d]   + __ldg(&b0[d]);
            nv[d] = s_part[0][3+d] + s_part[1][3+d] + s_part[2][3+d] + s_part[3][3+d] + __ldg(&b1[d]);
        }
        float io = 1.0f / (sqrtf(ov[0]*ov[0]+ov[1]*ov[1]+ov[2]*ov[2] + 1e-8f) + 1e-10f);
        ov[0] *= io; ov[1] *= io; ov[2] *= io;
        float in = 1.0f / (sqrtf(nv[0]*nv[0]+nv[1]*nv[1]+nv[2]*nv[2] + 1e-8f) + 1e-10f);
        nv[0] *= in; nv[1] *= in; nv[2] *= in;

        float r90[3];
        r90[0] = ov[1]*nv[2] - ov[2]*nv[1];
        r90[1] = ov[2]*nv[0] - ov[0]*nv[2];
        r90[2] = ov[0]*nv[1] - ov[1]*nv[0];
        float ir = 1.0f / (sqrtf(r90[0]*r90[0]+r90[1]*r90[1]+r90[2]*r90[2] + 1e-8f) + 1e-10f);
        r90[0] *= ir; r90[1] *= ir; r90[2] *= ir;

        float o0[3];
        o0[0] = r90[1]*nv[2] - r90[2]*nv[1];
        o0[1] = r90[2]*nv[0] - r90[0]*nv[2];
        o0[2] = r90[0]*nv[1] - r90[1]*nv[0];
        float i0 = 1.0f / (sqrtf(o0[0]*o0[0]+o0[1]*o0[1]+o0[2]*o0[2] + 1e-8f) + 1e-10f);
        o0[0] *= i0; o0[1] *= i0; o0[2] *= i0;

        s_rot[0] = o0[0];  s_rot[1] = o0[1];  s_rot[2] = o0[2];
        s_rot[3] = r90[0]; s_rot[4] = r90[1]; s_rot[5] = r90[2];
        s_rot[6] = nv[0];  s_rot[7] = nv[1];  s_rot[8] = nv[2];

#pragma unroll
        for (int d = 0; d < 3; d++) {
            out[OFF_ORIS + p * 3 + d] = ov[d];
            out[OFF_NORS + p * 3 + d] = nv[d];
        }
    }
    if (warp == 0) {
        unsigned m = s_mask[lane];
        int pc = __popc(m);
        int incl = pc;
#pragma unroll
        for (int o = 1; o < 32; o <<= 1) {
            int v = __shfl_up_sync(0xffffffffu, incl, o);
            if (lane >= o) incl += v;
        }
        int excl = incl - pc;
        if (lane == 31) s_cnt = (incl < NS) ? incl : NS;
        unsigned mm = m;
        int r = excl;
        while (mm && r < NS) {
            int bpos = __ffs(mm) - 1;
            s_nbr[r] = (lane << 5) + bpos;
            mm &= mm - 1;
            r++;
        }
    }
    __syncthreads();

    // ---- local coords -> cell; last-wins winner; compact ------------------------------
    int myCell = -1, myJ = 0;
    if (t < NS) {
        myJ = (t < s_cnt) ? s_nbr[t] : s_nbr[0];
        float lx = __ldg(&xb[myJ]) - cx;
        float ly = __ldg(&xb[NPTS + myJ]) - cy;
        float lz = __ldg(&xb[2 * NPTS + myJ]) - cz;
        int c[3];
#pragma unroll
        for (int d = 0; d < 3; d++) {
            float lp = lx * s_rot[d*3+0] + ly * s_rot[d*3+1] + lz * s_rot[d*3+2];
            float v = rintf((lp + 0.3f) / 0.6f * 6.0f);
            int ci = (int)v;
            ci = ci < 0 ? 0 : (ci > 6 ? 6 : ci);
            c[d] = ci;
        }
        myCell = c[0] * 7 + c[1] * 7 + c[2];   // reference quirk: both *g
        atomicMax(&s_win[myCell], t);
    }
    __syncthreads();
    if (t < NS && s_win[myCell] == t) {
        int w = atomicAdd(&s_nwin, 1);
        s_wlist[w] = (myCell << 10) | myJ;
    }
    __syncthreads();

    // ---- sparse feat_off: 4 winners/warp-iter, 8 lanes/winner, LDS.128 weights --------
    {
        const int nw = s_nwin;
        const float4* fb = (const float4*)(feat + ((long)b << 17));
        const int sub  = lane >> 3;
        const int lsub = lane & 7;

        for (int g = warp * 4; g < nw; g += 16) {
            int i = g + sub;
            bool valid = (i < nw);
            int pk   = s_wlist[valid ? i : 0];
            int cell = pk >> 10;
            int nbr  = pk & 1023;

            // channels c = lsub*4 + blk*32 + {0..3}
            float4 v0 = __ldg(&fb[(nbr << 5) + lsub]);
            float4 v1 = __ldg(&fb[(nbr << 5) + lsub + 8]);
            float4 v2 = __ldg(&fb[(nbr << 5) + lsub + 16]);
            float4 v3 = __ldg(&fb[(nbr << 5) + lsub + 24]);

            int k  = cell % 7;
            int p5 = (cell / 49) * 7 + (cell / 7) % 7;

            // transposed weights: [k][c][3]; 12 consecutive floats per blk
            const float4* wk = (const float4*)&s_wu[k * 384 + lsub * 12];
            float a0 = 0.f, a1 = 0.f, a2 = 0.f;
#pragma unroll
            for (int blk = 0; blk < 4; blk++) {
                float4 v = (blk == 0) ? v0 : (blk == 1) ? v1 : (blk == 2) ? v2 : v3;
                float4 w0 = wk[blk * 24 + 0];   // blk*96 floats = blk*24 float4
                float4 w1 = wk[blk * 24 + 1];
                float4 w2 = wk[blk * 24 + 2];
                a0 += v.x * w0.x + v.y * w0.w + v.z * w1.z + v.w * w2.y;
                a1 += v.x * w0.y + v.y * w1.x + v.z * w1.w + v.w * w2.z;
                a2 += v.x * w0.z + v.y * w1.y + v.z * w2.x + v.w * w2.w;
            }

            // reduce within each 8-lane group
            a0 += __shfl_xor_sync(0xffffffffu, a0, 4);
            a1 += __shfl_xor_sync(0xffffffffu, a1, 4);
            a2 += __shfl_xor_sync(0xffffffffu, a2, 4);
            a0 += __shfl_xor_sync(0xffffffffu, a0, 2);
            a1 += __shfl_xor_sync(0xffffffffu, a1, 2);
            a2 += __shfl_xor_sync(0xffffffffu, a2, 2);
            a0 += __shfl_xor_sync(0xffffffffu, a0, 1);
            a1 += __shfl_xor_sync(0xffffffffu, a1, 1);
            a2 += __shfl_xor_sync(0xffffffffu, a2, 1);

            if (lsub == 0 && valid) {
                atomicAdd(&s_off[p5 * 3 + 0], a0);
                atomicAdd(&s_off[p5 * 3 + 1], a1);
                atomicAdd(&s_off[p5 * 3 + 2], a2);
            }
        }
    }
    __syncthreads();

    // ---- up = vals + feat_off; rotate back; write outputs -------------------------------
    if (t < 49) {
        int s = t;
        float u0 = (float)(s / 7 - 3) * 0.1f + s_off[s * 3 + 0];
        float u1 = (float)(s % 7 - 3) * 0.1f + s_off[s * 3 + 1];
        float u2 = s_off[s * 3 + 2];
        float w[3];
#pragma unroll
        for (int d = 0; d < 3; d++)
            w[d] = u0 * s_rot[d] + u1 * s_rot[3 + d] + u2 * s_rot[6 + d]
                 + (d == 0 ? cx : (d == 1 ? cy : cz));

        float* o_up = out + OFF_PTSUP + (p * 49 + s) * 3;
        o_up[0] = w[0]; o_up[1] = w[1]; o_up[2] = w[2];

        if (s == 24) {
            float* o_of = out + OFF_OFFSET + p * 3;
            o_of[0] = w[0]; o_of[1] = w[1]; o_of[2] = w[2];
        }
        unsigned m = s_upmask[s];
        while (m) {
            int q = __ffs(m) - 1;
            m &= m - 1;
            float* o_u = out + OFF_UPS + (p * 16 + q) * 3;
            o_u[0] = w[0]; o_u[1] = w[1]; o_u[2] = w[2];
        }
    }
}

extern "C" void kernel_launch(void* const* d_in, const int* in_sizes, int n_in,
                              void* d_out, int out_size)
{
    const float* xyz   = (const float*)d_in[0];
    const float* feat  = (const float*)d_in[1];
    const float* W0    = (const float*)d_in[2];
    const float* b0    = (const float*)d_in[3];
    const float* W1    = (const float*)d_in[4];
    const float* b1    = (const float*)d_in[5];
    const float* Wu    = (const float*)d_in[6];
    const int*   index = (const int*)d_in[7];
    float* out = (float*)d_out;

    ipunet_kernel<<<2048, 128>>>(xyz, feat, W0, b0, W1, b1, Wu, index, out);
}